// round 1
// baseline (speedup 1.0000x reference)
#include <cuda_runtime.h>
#include <math.h>

#define T_   16
#define SPA  2048
#define C_   768
#define NH   12
#define HD   64
#define N1   2304
#define M_   (T_*SPA)   // 32768

// Scratch (static device allocations; no cudaMalloc allowed)
__device__ float g_rstd[T_*NH];                       // 192
__device__ float g_qkv[(size_t)SPA*NH*T_*192];        // 75,497,472 floats
__device__ float g_a2 [(size_t)M_*C_];                // 25,165,824 floats

// ---------------------------------------------------------------------------
// Kernel 1: RMS groupnorm statistics. One block per (t, group).
// Group (t,g) covers x[t, g*64:(g+1)*64, :, :, :] = 131072 contiguous floats.
// ---------------------------------------------------------------------------
__global__ void gn_stats_kernel(const float* __restrict__ x) {
    int g = blockIdx.x % NH;
    int t = blockIdx.x / NH;
    const float4* p = (const float4*)(x + (size_t)t*C_*SPA + (size_t)g*HD*SPA);
    float ss = 0.f;
    for (int i = threadIdx.x; i < (HD*SPA)/4; i += blockDim.x) {
        float4 v = p[i];
        ss += v.x*v.x + v.y*v.y + v.z*v.z + v.w*v.w;
    }
    __shared__ float red[256];
    red[threadIdx.x] = ss;
    __syncthreads();
    for (int o = 128; o > 0; o >>= 1) {
        if (threadIdx.x < o) red[threadIdx.x] += red[threadIdx.x + o];
        __syncthreads();
    }
    if (threadIdx.x == 0)
        g_rstd[t*NH + g] = rsqrtf(red[0] * (1.f/(HD*SPA)) + 1e-6f);
}

// ---------------------------------------------------------------------------
// Kernel 2: QKV GEMM. C[m=(t,s), n] = sum_c A[m,c]*W[n,c] + bias[n]
//   A[m,c] = x[t,c,s] * rstd[t, c/64] * norm1_weight[c]
// Output scattered to g_qkv[s, h, t, j] with n = h*192 + j.
// 64x64 tile, 256 threads, 4x4 microtile.
// ---------------------------------------------------------------------------
__global__ void qkv_gemm_kernel(const float* __restrict__ x,
                                const float* __restrict__ nw,
                                const float* __restrict__ w,
                                const float* __restrict__ bias) {
    __shared__ __align__(16) float As[16][68];
    __shared__ __align__(16) float Bs[16][68];
    int bm = blockIdx.x * 64, bn = blockIdx.y * 64;
    int t  = bm >> 11, s0 = bm & (SPA-1);
    int tid = threadIdx.x;
    int tx = tid & 15, ty = tid >> 4;
    float acc[4][4] = {};
    const float* xbase = x + (size_t)t*C_*SPA + s0;

    for (int k0 = 0; k0 < C_; k0 += 16) {
        #pragma unroll
        for (int r = 0; r < 4; r++) {
            int e  = tid + r*256;
            int kl = e >> 6, ml = e & 63;
            int c  = k0 + kl;
            As[kl][ml] = xbase[(size_t)c*SPA + ml] * (g_rstd[t*NH + (c>>6)] * nw[c]);
        }
        #pragma unroll
        for (int r = 0; r < 4; r++) {
            int e  = tid + r*256;
            int nl = e >> 4, kl = e & 15;
            Bs[kl][nl] = w[(size_t)(bn+nl)*C_ + k0 + kl];
        }
        __syncthreads();
        #pragma unroll
        for (int k = 0; k < 16; k++) {
            float4 a = *(const float4*)&As[k][ty<<2];
            float4 b = *(const float4*)&Bs[k][tx<<2];
            acc[0][0] += a.x*b.x; acc[0][1] += a.x*b.y; acc[0][2] += a.x*b.z; acc[0][3] += a.x*b.w;
            acc[1][0] += a.y*b.x; acc[1][1] += a.y*b.y; acc[1][2] += a.y*b.z; acc[1][3] += a.y*b.w;
            acc[2][0] += a.z*b.x; acc[2][1] += a.z*b.y; acc[2][2] += a.z*b.z; acc[2][3] += a.z*b.w;
            acc[3][0] += a.w*b.x; acc[3][1] += a.w*b.y; acc[3][2] += a.w*b.z; acc[3][3] += a.w*b.w;
        }
        __syncthreads();
    }

    int n0 = bn + (tx<<2);
    int h  = n0 / 192, j0 = n0 % 192;     // 192 % 64 == 0 => h fixed per tile column group
    float b0 = bias[n0], b1 = bias[n0+1], b2 = bias[n0+2], b3 = bias[n0+3];
    #pragma unroll
    for (int i = 0; i < 4; i++) {
        int s = s0 + (ty<<2) + i;
        float4 v = make_float4(acc[i][0]+b0, acc[i][1]+b1, acc[i][2]+b2, acc[i][3]+b3);
        *(float4*)&g_qkv[(((size_t)s*NH + h)*T_ + t)*192 + j0] = v;
    }
}

// ---------------------------------------------------------------------------
// Kernel 3: attention. One 128-thread block per (s, head).
// LN(q), LN(k), S = q k^T / 8 + relbias, softmax over t, out = S v.
// Writes g_a2[(i*SPA + s)*768 + h*64 + d]  (i = sequence/query index).
// ---------------------------------------------------------------------------
__global__ void attn_kernel(const float* __restrict__ qsc, const float* __restrict__ qbi,
                            const float* __restrict__ ksc, const float* __restrict__ kbi,
                            const float* __restrict__ tab) {
    int sh = blockIdx.x;
    int h  = sh % NH, s = sh / NH;
    __shared__ float qs[16][65], ks[16][65], vs[16][65], P[16][17];
    int tid  = threadIdx.x;
    int row  = tid >> 3;          // 0..15 : sequence row
    int part = tid & 7;           // 8 threads per row, 8 elems each
    const float* base = g_qkv + (size_t)sh*(T_*192) + row*192 + part*8;

    // ---- layernorm Q ----
    {
        float v0[8];
        #pragma unroll
        for (int e = 0; e < 8; e++) v0[e] = base[e];
        float sum = 0.f;
        #pragma unroll
        for (int e = 0; e < 8; e++) sum += v0[e];
        sum += __shfl_xor_sync(0xffffffffu, sum, 1);
        sum += __shfl_xor_sync(0xffffffffu, sum, 2);
        sum += __shfl_xor_sync(0xffffffffu, sum, 4);
        float mu = sum * (1.f/64.f);
        float var = 0.f;
        #pragma unroll
        for (int e = 0; e < 8; e++) { float d = v0[e]-mu; var += d*d; }
        var += __shfl_xor_sync(0xffffffffu, var, 1);
        var += __shfl_xor_sync(0xffffffffu, var, 2);
        var += __shfl_xor_sync(0xffffffffu, var, 4);
        float r = rsqrtf(var * (1.f/64.f) + 1e-6f);
        #pragma unroll
        for (int e = 0; e < 8; e++) {
            int j = part*8 + e;
            qs[row][j] = (v0[e]-mu)*r*qsc[j] + qbi[j];
        }
    }
    // ---- layernorm K ----
    {
        float v0[8];
        #pragma unroll
        for (int e = 0; e < 8; e++) v0[e] = base[64 + e];
        float sum = 0.f;
        #pragma unroll
        for (int e = 0; e < 8; e++) sum += v0[e];
        sum += __shfl_xor_sync(0xffffffffu, sum, 1);
        sum += __shfl_xor_sync(0xffffffffu, sum, 2);
        sum += __shfl_xor_sync(0xffffffffu, sum, 4);
        float mu = sum * (1.f/64.f);
        float var = 0.f;
        #pragma unroll
        for (int e = 0; e < 8; e++) { float d = v0[e]-mu; var += d*d; }
        var += __shfl_xor_sync(0xffffffffu, var, 1);
        var += __shfl_xor_sync(0xffffffffu, var, 2);
        var += __shfl_xor_sync(0xffffffffu, var, 4);
        float r = rsqrtf(var * (1.f/64.f) + 1e-6f);
        #pragma unroll
        for (int e = 0; e < 8; e++) {
            int j = part*8 + e;
            ks[row][j] = (v0[e]-mu)*r*ksc[j] + kbi[j];
        }
    }
    // ---- V (raw) ----
    #pragma unroll
    for (int e = 0; e < 8; e++) vs[row][part*8 + e] = base[128 + e];
    __syncthreads();

    // ---- logits + relative bias ----
    const float inv_log16_x8 = 8.f / logf(16.f);
    for (int e = tid; e < 256; e += 128) {
        int i = e >> 4, j = e & 15;
        float d = 0.f;
        #pragma unroll
        for (int c = 0; c < 64; c++) d += qs[i][c]*ks[j][c];
        int rp  = j - i;
        int ret = (rp > 0) ? 16 : 0;
        int n   = rp < 0 ? -rp : rp;
        int bkt;
        if (n < 8) bkt = ret + n;
        else {
            int vl = 8 + (int)(logf((float)n * 0.125f) * inv_log16_x8);
            bkt = ret + (vl < 15 ? vl : 15);
        }
        P[i][j] = d * 0.125f + tab[bkt*NH + h];
    }
    __syncthreads();

    // ---- softmax per row ----
    if (tid < 16) {
        float m = -1e30f;
        #pragma unroll
        for (int j = 0; j < 16; j++) m = fmaxf(m, P[tid][j]);
        float sum = 0.f;
        #pragma unroll
        for (int j = 0; j < 16; j++) { float e = expf(P[tid][j]-m); P[tid][j] = e; sum += e; }
        float inv = 1.f / sum;
        #pragma unroll
        for (int j = 0; j < 16; j++) P[tid][j] *= inv;
    }
    __syncthreads();

    // ---- out = P @ V ----
    float o[8] = {0,0,0,0,0,0,0,0};
    #pragma unroll
    for (int t2 = 0; t2 < 16; t2++) {
        float p = P[row][t2];
        #pragma unroll
        for (int e = 0; e < 8; e++) o[e] += p * vs[t2][part*8 + e];
    }
    float* op = g_a2 + ((size_t)row*SPA + s)*C_ + h*HD + part*8;
    *(float4*)&op[0] = make_float4(o[0], o[1], o[2], o[3]);
    *(float4*)&op[4] = make_float4(o[4], o[5], o[6], o[7]);
}

// ---------------------------------------------------------------------------
// Kernel 4: output GEMM + bias + residual.
// y[t, n, s] = sum_c g_a2[(t,s), c] * Wout[n, c] + bout[n] + x[t, n, s]
// ---------------------------------------------------------------------------
__global__ void out_gemm_kernel(const float* __restrict__ x,
                                const float* __restrict__ w,
                                const float* __restrict__ bias,
                                float* __restrict__ y) {
    __shared__ __align__(16) float As[16][68];
    __shared__ __align__(16) float Bs[16][68];
    int bm = blockIdx.x * 64, bn = blockIdx.y * 64;
    int t  = bm >> 11, s0 = bm & (SPA-1);
    int tid = threadIdx.x;
    int tx = tid & 15, ty = tid >> 4;
    float acc[4][4] = {};

    for (int k0 = 0; k0 < C_; k0 += 16) {
        #pragma unroll
        for (int r = 0; r < 4; r++) {
            int e  = tid + r*256;
            int ml = e >> 4, kl = e & 15;
            As[kl][ml] = g_a2[(size_t)(bm+ml)*C_ + k0 + kl];
        }
        #pragma unroll
        for (int r = 0; r < 4; r++) {
            int e  = tid + r*256;
            int nl = e >> 4, kl = e & 15;
            Bs[kl][nl] = w[(size_t)(bn+nl)*C_ + k0 + kl];
        }
        __syncthreads();
        #pragma unroll
        for (int k = 0; k < 16; k++) {
            float4 a = *(const float4*)&As[k][ty<<2];
            float4 b = *(const float4*)&Bs[k][tx<<2];
            acc[0][0] += a.x*b.x; acc[0][1] += a.x*b.y; acc[0][2] += a.x*b.z; acc[0][3] += a.x*b.w;
            acc[1][0] += a.y*b.x; acc[1][1] += a.y*b.y; acc[1][2] += a.y*b.z; acc[1][3] += a.y*b.w;
            acc[2][0] += a.z*b.x; acc[2][1] += a.z*b.y; acc[2][2] += a.z*b.z; acc[2][3] += a.z*b.w;
            acc[3][0] += a.w*b.x; acc[3][1] += a.w*b.y; acc[3][2] += a.w*b.z; acc[3][3] += a.w*b.w;
        }
        __syncthreads();
    }

    #pragma unroll
    for (int jj = 0; jj < 4; jj++) {
        int n = bn + (tx<<2) + jj;
        size_t off = (size_t)t*C_*SPA + (size_t)n*SPA + s0 + (ty<<2);
        float4 rx = *(const float4*)&x[off];
        float bb  = bias[n];
        float4 v = make_float4(acc[0][jj]+bb+rx.x, acc[1][jj]+bb+rx.y,
                               acc[2][jj]+bb+rx.z, acc[3][jj]+bb+rx.w);
        *(float4*)&y[off] = v;
    }
}

// ---------------------------------------------------------------------------
extern "C" void kernel_launch(void* const* d_in, const int* in_sizes, int n_in,
                              void* d_out, int out_size) {
    const float* x     = (const float*)d_in[0];
    const float* nw    = (const float*)d_in[1];
    const float* w_in  = (const float*)d_in[2];
    const float* b_in  = (const float*)d_in[3];
    const float* qsc   = (const float*)d_in[4];
    const float* qbi   = (const float*)d_in[5];
    const float* ksc   = (const float*)d_in[6];
    const float* kbi   = (const float*)d_in[7];
    const float* tab   = (const float*)d_in[8];
    const float* w_out = (const float*)d_in[9];
    const float* b_out = (const float*)d_in[10];
    float* y = (float*)d_out;

    gn_stats_kernel<<<T_*NH, 256>>>(x);
    qkv_gemm_kernel<<<dim3(M_/64, N1/64), 256>>>(x, nw, w_in, b_in);
    attn_kernel<<<SPA*NH, 128>>>(qsc, qbi, ksc, kbi, tab);
    out_gemm_kernel<<<dim3(M_/64, C_/64), 256>>>(x, w_out, b_out, y);
}

// round 3
// speedup vs baseline: 2.0325x; 2.0325x over previous
#include <cuda_runtime.h>
#include <cuda_bf16.h>
#include <math.h>
#include <stdint.h>

#define T_   16
#define SPA  2048
#define C_   768
#define NH   12
#define HD   64
#define N1   2304
#define M_   (T_*SPA)   // 32768

// ---------------- scratch (static device allocations) ----------------------
__device__ float g_rstd[T_*NH];
__device__ float g_qkv[(size_t)SPA*NH*T_*192];
__device__ __nv_bfloat16 g_xh[(size_t)M_*C_], g_xl[(size_t)M_*C_];
__device__ __nv_bfloat16 g_wih[(size_t)N1*C_], g_wil[(size_t)N1*C_];
__device__ __nv_bfloat16 g_woh[(size_t)C_*C_], g_wol[(size_t)C_*C_];
__device__ __nv_bfloat16 g_oh[(size_t)M_*C_], g_ol[(size_t)M_*C_];

// ---------------- helpers ---------------------------------------------------
static __device__ __forceinline__ uint32_t smem_u32(const void* p) {
    uint32_t a;
    asm("{ .reg .u64 t; cvta.to.shared.u64 t, %1; cvt.u32.u64 %0, t; }" : "=r"(a) : "l"(p));
    return a;
}
static __device__ __forceinline__ unsigned pk2(float a, float b) {
    unsigned short ua = __bfloat16_as_ushort(__float2bfloat16(a));
    unsigned short ub = __bfloat16_as_ushort(__float2bfloat16(b));
    return (unsigned)ua | ((unsigned)ub << 16);
}
static __device__ __forceinline__ void split2(float a, float b, unsigned& hi, unsigned& lo) {
    __nv_bfloat16 ha = __float2bfloat16(a), hb = __float2bfloat16(b);
    hi = (unsigned)__bfloat16_as_ushort(ha) | ((unsigned)__bfloat16_as_ushort(hb) << 16);
    lo = pk2(a - __bfloat162float(ha), b - __bfloat162float(hb));
}

#define CP16(smem, gp) \
    asm volatile("cp.async.cg.shared.global [%0], [%1], 16;" :: "r"(smem), "l"(gp) : "memory")
#define CP_COMMIT() asm volatile("cp.async.commit_group;" ::: "memory")
#define CP_WAIT0()  asm volatile("cp.async.wait_group 0;" ::: "memory")

#define LDSM4(r, addr) \
    asm volatile("ldmatrix.sync.aligned.m8n8.x4.shared.b16 {%0,%1,%2,%3}, [%4];" \
        : "=r"((r)[0]), "=r"((r)[1]), "=r"((r)[2]), "=r"((r)[3]) : "r"(addr))

#define MMA(d, a, b0, b1) \
    asm volatile("mma.sync.aligned.m16n8k16.row.col.f32.bf16.bf16.f32 " \
        "{%0,%1,%2,%3}, {%4,%5,%6,%7}, {%8,%9}, {%0,%1,%2,%3};" \
        : "+f"((d)[0]), "+f"((d)[1]), "+f"((d)[2]), "+f"((d)[3]) \
        : "r"((a)[0]), "r"((a)[1]), "r"((a)[2]), "r"((a)[3]), "r"(b0), "r"(b1))

// ---------------------------------------------------------------------------
// Kernel 1: RMS groupnorm stats
// ---------------------------------------------------------------------------
__global__ void gn_stats_kernel(const float* __restrict__ x) {
    int g = blockIdx.x % NH, t = blockIdx.x / NH;
    const float4* p = (const float4*)(x + (size_t)t*C_*SPA + (size_t)g*HD*SPA);
    float ss = 0.f;
    for (int i = threadIdx.x; i < (HD*SPA)/4; i += blockDim.x) {
        float4 v = p[i];
        ss += v.x*v.x + v.y*v.y + v.z*v.z + v.w*v.w;
    }
    __shared__ float red[256];
    red[threadIdx.x] = ss;
    __syncthreads();
    for (int o = 128; o > 0; o >>= 1) {
        if (threadIdx.x < o) red[threadIdx.x] += red[threadIdx.x + o];
        __syncthreads();
    }
    if (threadIdx.x == 0)
        g_rstd[t*NH + g] = rsqrtf(red[0] * (1.f/(HD*SPA)) + 1e-6f);
}

// ---------------------------------------------------------------------------
// Kernel 2: transpose + scale + bf16-split x -> g_xh/g_xl  [m=(t,s)][c]
// ---------------------------------------------------------------------------
__global__ void prep_x_kernel(const float* __restrict__ x, const float* __restrict__ nw) {
    __shared__ float tile[64][65];
    int bm = blockIdx.x * 64, c0 = blockIdx.y * 64;
    int t = bm >> 11, s0 = bm & (SPA-1);
    int tid = threadIdx.x;
    int sl = tid & 63, cb = tid >> 6;
    #pragma unroll
    for (int r = 0; r < 16; r++) {
        int c = cb*16 + r, cg = c0 + c;
        float sc = g_rstd[t*NH + (cg >> 6)] * nw[cg];
        tile[sl][c] = x[(size_t)t*C_*SPA + (size_t)cg*SPA + s0 + sl] * sc;
    }
    __syncthreads();
    int cl = tid & 31, mb = tid >> 5;
    #pragma unroll
    for (int r = 0; r < 8; r++) {
        int m = mb*8 + r;
        unsigned hi, lo;
        split2(tile[m][2*cl], tile[m][2*cl+1], hi, lo);
        size_t o = (size_t)(bm+m)*(C_/2) + (c0 >> 1) + cl;
        ((unsigned*)g_xh)[o] = hi;
        ((unsigned*)g_xl)[o] = lo;
    }
}

// ---------------------------------------------------------------------------
// Kernel 3: bf16-split both weight matrices (k-contiguous already)
// ---------------------------------------------------------------------------
__global__ void prep_w_kernel(const float* __restrict__ win, const float* __restrict__ wout) {
    int i = blockIdx.x * 256 + threadIdx.x;
    const int NI = N1*C_/4;
    float4 v; unsigned* dh; unsigned* dl; int j;
    if (i < NI) { v = ((const float4*)win)[i]; dh = (unsigned*)g_wih; dl = (unsigned*)g_wil; j = i; }
    else        { j = i - NI; v = ((const float4*)wout)[j]; dh = (unsigned*)g_woh; dl = (unsigned*)g_wol; }
    unsigned h0, l0, h1, l1;
    split2(v.x, v.y, h0, l0);
    split2(v.z, v.w, h1, l1);
    dh[2*j] = h0; dh[2*j+1] = h1;
    dl[2*j] = l0; dl[2*j+1] = l1;
}

// ---------------------------------------------------------------------------
// MMA mainloop: CTA 128x128, K=768, chunks of k32 stored as 128B rows
// [hi 64B | lo 64B], SW128 swizzle, double buffered via cp.async.
// A region at buf+0, B region at buf+16384; buffers at 0 / 32768.
// acc[mt][n8][4]: mt in {0,1} (m16 tiles), n8 in 0..7 (n8 tiles).
// ---------------------------------------------------------------------------
static __device__ __forceinline__ void mma_mainloop(
        float acc[2][8][4], const char* aSrc, const char* bSrc, uint32_t sb) {
    int tid = threadIdx.x;
    int lid = tid & 31, wid = tid >> 5;
    int wm = (wid & 3) * 32, wn = (wid >> 2) * 64;
    int r  = tid >> 1, hf = tid & 1;

    uint32_t stRow = (uint32_t)(r * 128);
    uint32_t xld   = (uint32_t)((r & 7) << 4);

    uint32_t xr   = (uint32_t)((lid & 7) << 4);
    uint32_t aSel = (uint32_t)(((lid >> 4) & 1) << 4);
    uint32_t bSel = (uint32_t)(((lid >> 3) & 1) << 4);
    uint32_t arb[2], brb[4];
    #pragma unroll
    for (int mt = 0; mt < 2; mt++)
        arb[mt] = (uint32_t)((wm + mt*16 + (lid & 15)) * 128);
    #pragma unroll
    for (int nt = 0; nt < 4; nt++)
        brb[nt] = (uint32_t)((wn + nt*16 + (lid & 7) + (((lid >> 4) & 1) << 3)) * 128);

    // prologue: prefetch chunk 0
    {
        uint32_t dst = sb + stRow;
        #pragma unroll
        for (int i = 0; i < 4; i++) {
            uint32_t o = (uint32_t)((hf << 6) | (i << 4)) ^ xld;
            CP16(dst + o,         aSrc + i*16);
            CP16(dst + 16384 + o, bSrc + i*16);
        }
        CP_COMMIT();
    }

    #pragma unroll 2
    for (int c = 0; c < 24; c++) {
        CP_WAIT0();
        __syncthreads();
        if (c + 1 < 24) {
            uint32_t dst = sb + (uint32_t)(((c+1) & 1) * 32768) + stRow;
            const char* ap = aSrc + (size_t)(c+1)*64;
            const char* bp = bSrc + (size_t)(c+1)*64;
            #pragma unroll
            for (int i = 0; i < 4; i++) {
                uint32_t o = (uint32_t)((hf << 6) | (i << 4)) ^ xld;
                CP16(dst + o,         ap + i*16);
                CP16(dst + 16384 + o, bp + i*16);
            }
            CP_COMMIT();
        }
        uint32_t bo = (uint32_t)((c & 1) * 32768);
        #pragma unroll
        for (int kk = 0; kk < 2; kk++) {
            uint32_t cb = (uint32_t)(kk << 5);
            uint32_t ah[2][4], al[2][4], bh[4][4], bl[4][4];
            #pragma unroll
            for (int mt = 0; mt < 2; mt++) {
                uint32_t base = sb + bo + arb[mt];
                LDSM4(ah[mt], base + (((0u<<6) | cb | aSel) ^ xr));
                LDSM4(al[mt], base + (((1u<<6) | cb | aSel) ^ xr));
            }
            #pragma unroll
            for (int nt = 0; nt < 4; nt++) {
                uint32_t base = sb + bo + 16384 + brb[nt];
                LDSM4(bh[nt], base + (((0u<<6) | cb | bSel) ^ xr));
                LDSM4(bl[nt], base + (((1u<<6) | cb | bSel) ^ xr));
            }
            // product HH
            #pragma unroll
            for (int nt = 0; nt < 4; nt++)
                #pragma unroll
                for (int n8 = 0; n8 < 2; n8++)
                    #pragma unroll
                    for (int mt = 0; mt < 2; mt++)
                        MMA(acc[mt][nt*2+n8], ah[mt], bh[nt][n8*2], bh[nt][n8*2+1]);
            // product HL
            #pragma unroll
            for (int nt = 0; nt < 4; nt++)
                #pragma unroll
                for (int n8 = 0; n8 < 2; n8++)
                    #pragma unroll
                    for (int mt = 0; mt < 2; mt++)
                        MMA(acc[mt][nt*2+n8], ah[mt], bl[nt][n8*2], bl[nt][n8*2+1]);
            // product LH
            #pragma unroll
            for (int nt = 0; nt < 4; nt++)
                #pragma unroll
                for (int n8 = 0; n8 < 2; n8++)
                    #pragma unroll
                    for (int mt = 0; mt < 2; mt++)
                        MMA(acc[mt][nt*2+n8], al[mt], bh[nt][n8*2], bh[nt][n8*2+1]);
        }
    }
}

// Stage accumulators into smem as [128][132] f32
static __device__ __forceinline__ void stage_acc(float acc[2][8][4], float* st) {
    int tid = threadIdx.x, lid = tid & 31, wid = tid >> 5;
    int wm = (wid & 3) * 32, wn = (wid >> 2) * 64;
    int qr = lid >> 2, qc = (lid & 3) * 2;
    #pragma unroll
    for (int mt = 0; mt < 2; mt++)
        #pragma unroll
        for (int n8 = 0; n8 < 8; n8++) {
            float* p0 = st + (wm + mt*16 + qr)*132 + wn + n8*8 + qc;
            p0[0] = acc[mt][n8][0];
            p0[1] = acc[mt][n8][1];
            p0[8*132]   = acc[mt][n8][2];
            p0[8*132+1] = acc[mt][n8][3];
        }
}

// ---------------------------------------------------------------------------
// Kernel 4: QKV GEMM (tensor cores via mma.sync)
// ---------------------------------------------------------------------------
__global__ void __launch_bounds__(256, 1) qkv_gemm_tc(const float* __restrict__ bias) {
    extern __shared__ char smem[];
    uint32_t sb = smem_u32(smem);
    int tid = threadIdx.x;
    int bn = blockIdx.x * 128, bm = blockIdx.y * 128;
    int r = tid >> 1, hf = tid & 1;
    const char* aSrc = (const char*)((hf ? g_xl  : g_xh ) + (size_t)(bm + r)*C_);
    const char* bSrc = (const char*)((hf ? g_wil : g_wih) + (size_t)(bn + r)*C_);

    float acc[2][8][4] = {};
    mma_mainloop(acc, aSrc, bSrc, sb);
    __syncthreads();
    float* st = (float*)smem;
    stage_acc(acc, st);
    __syncthreads();

    int t = bm >> 11, s = (bm & (SPA-1)) + (tid >> 1);
    int n0 = bn + (tid & 1) * 64;
    int h = n0 / 192, j0 = n0 % 192;
    float* dst = &g_qkv[(((size_t)s*NH + h)*T_ + t)*192 + j0];
    const float* src = st + (tid >> 1)*132 + (tid & 1)*64;
    #pragma unroll
    for (int i = 0; i < 16; i++) {
        float4 v  = *(const float4*)(src + i*4);
        float4 bv = *(const float4*)(bias + n0 + i*4);
        v.x += bv.x; v.y += bv.y; v.z += bv.z; v.w += bv.w;
        *(float4*)(dst + i*4) = v;
    }
}

// ---------------------------------------------------------------------------
// Kernel 5: attention (fp32), writes split-bf16 output for the out GEMM
// ---------------------------------------------------------------------------
__global__ void attn_kernel(const float* __restrict__ qsc, const float* __restrict__ qbi,
                            const float* __restrict__ ksc, const float* __restrict__ kbi,
                            const float* __restrict__ tab) {
    int sh = blockIdx.x;
    int h = sh % NH, s = sh / NH;
    __shared__ float qs[16][65], ks[16][65], vs[16][65], P[16][17];
    int tid = threadIdx.x;
    int row = tid >> 3, part = tid & 7;
    const float* base = g_qkv + (size_t)sh*(T_*192) + row*192 + part*8;

    {
        float v0[8];
        #pragma unroll
        for (int e = 0; e < 8; e++) v0[e] = base[e];
        float sum = 0.f;
        #pragma unroll
        for (int e = 0; e < 8; e++) sum += v0[e];
        sum += __shfl_xor_sync(~0u, sum, 1); sum += __shfl_xor_sync(~0u, sum, 2); sum += __shfl_xor_sync(~0u, sum, 4);
        float mu = sum * (1.f/64.f), var = 0.f;
        #pragma unroll
        for (int e = 0; e < 8; e++) { float d = v0[e]-mu; var += d*d; }
        var += __shfl_xor_sync(~0u, var, 1); var += __shfl_xor_sync(~0u, var, 2); var += __shfl_xor_sync(~0u, var, 4);
        float rr = rsqrtf(var * (1.f/64.f) + 1e-6f);
        #pragma unroll
        for (int e = 0; e < 8; e++) { int j = part*8+e; qs[row][j] = (v0[e]-mu)*rr*qsc[j] + qbi[j]; }
    }
    {
        float v0[8];
        #pragma unroll
        for (int e = 0; e < 8; e++) v0[e] = base[64+e];
        float sum = 0.f;
        #pragma unroll
        for (int e = 0; e < 8; e++) sum += v0[e];
        sum += __shfl_xor_sync(~0u, sum, 1); sum += __shfl_xor_sync(~0u, sum, 2); sum += __shfl_xor_sync(~0u, sum, 4);
        float mu = sum * (1.f/64.f), var = 0.f;
        #pragma unroll
        for (int e = 0; e < 8; e++) { float d = v0[e]-mu; var += d*d; }
        var += __shfl_xor_sync(~0u, var, 1); var += __shfl_xor_sync(~0u, var, 2); var += __shfl_xor_sync(~0u, var, 4);
        float rr = rsqrtf(var * (1.f/64.f) + 1e-6f);
        #pragma unroll
        for (int e = 0; e < 8; e++) { int j = part*8+e; ks[row][j] = (v0[e]-mu)*rr*ksc[j] + kbi[j]; }
    }
    #pragma unroll
    for (int e = 0; e < 8; e++) vs[row][part*8+e] = base[128+e];
    __syncthreads();

    const float inv_log16_x8 = 8.f / logf(16.f);
    for (int e = tid; e < 256; e += 128) {
        int i = e >> 4, j = e & 15;
        float d = 0.f;
        #pragma unroll
        for (int c = 0; c < 64; c++) d += qs[i][c]*ks[j][c];
        int rp = j - i;
        int ret = (rp > 0) ? 16 : 0;
        int n = rp < 0 ? -rp : rp;
        int bkt;
        if (n < 8) bkt = ret + n;
        else {
            int vl = 8 + (int)(logf((float)n * 0.125f) * inv_log16_x8);
            bkt = ret + (vl < 15 ? vl : 15);
        }
        P[i][j] = d * 0.125f + tab[bkt*NH + h];
    }
    __syncthreads();
    if (tid < 16) {
        float m = -1e30f;
        #pragma unroll
        for (int j = 0; j < 16; j++) m = fmaxf(m, P[tid][j]);
        float sum = 0.f;
        #pragma unroll
        for (int j = 0; j < 16; j++) { float e = expf(P[tid][j]-m); P[tid][j] = e; sum += e; }
        float inv = 1.f / sum;
        #pragma unroll
        for (int j = 0; j < 16; j++) P[tid][j] *= inv;
    }
    __syncthreads();

    float o[8] = {0,0,0,0,0,0,0,0};
    #pragma unroll
    for (int t2 = 0; t2 < 16; t2++) {
        float p = P[row][t2];
        #pragma unroll
        for (int e = 0; e < 8; e++) o[e] += p * vs[t2][part*8+e];
    }
    unsigned H[4], L[4];
    #pragma unroll
    for (int e = 0; e < 4; e++) split2(o[2*e], o[2*e+1], H[e], L[e]);
    size_t off = ((size_t)row*SPA + s)*C_ + h*HD + part*8;
    *(uint4*)(g_oh + off) = make_uint4(H[0], H[1], H[2], H[3]);
    *(uint4*)(g_ol + off) = make_uint4(L[0], L[1], L[2], L[3]);
}

// ---------------------------------------------------------------------------
// Kernel 6: output GEMM + bias + residual
// ---------------------------------------------------------------------------
__global__ void __launch_bounds__(256, 1) out_gemm_tc(const float* __restrict__ x,
                                                      const float* __restrict__ bias,
                                                      float* __restrict__ y) {
    extern __shared__ char smem[];
    uint32_t sb = smem_u32(smem);
    int tid = threadIdx.x;
    int bn = blockIdx.x * 128, bm = blockIdx.y * 128;
    int r = tid >> 1, hf = tid & 1;
    const char* aSrc = (const char*)((hf ? g_ol  : g_oh ) + (size_t)(bm + r)*C_);
    const char* bSrc = (const char*)((hf ? g_wol : g_woh) + (size_t)(bn + r)*C_);

    float acc[2][8][4] = {};
    mma_mainloop(acc, aSrc, bSrc, sb);
    __syncthreads();
    float* st = (float*)smem;
    stage_acc(acc, st);
    __syncthreads();

    int n = bn + (tid >> 1);
    int sh_ = tid & 1;
    int t = bm >> 11, s0 = bm & (SPA-1);
    size_t off = (size_t)t*C_*SPA + (size_t)n*SPA + s0 + sh_*64;
    float bb = bias[n];
    const float* src = st + sh_*64*132 + (n - bn);
    #pragma unroll
    for (int i = 0; i < 64; i += 4) {
        float4 rx = *(const float4*)(x + off + i);
        float4 v = make_float4(src[(i+0)*132], src[(i+1)*132],
                               src[(i+2)*132], src[(i+3)*132]);
        v.x += bb + rx.x; v.y += bb + rx.y; v.z += bb + rx.z; v.w += bb + rx.w;
        *(float4*)(y + off + i) = v;
    }
}

// ---------------------------------------------------------------------------
#define SMEM_GEMM 67584

extern "C" void kernel_launch(void* const* d_in, const int* in_sizes, int n_in,
                              void* d_out, int out_size) {
    const float* x     = (const float*)d_in[0];
    const float* nw    = (const float*)d_in[1];
    const float* w_in  = (const float*)d_in[2];
    const float* b_in  = (const float*)d_in[3];
    const float* qsc   = (const float*)d_in[4];
    const float* qbi   = (const float*)d_in[5];
    const float* ksc   = (const float*)d_in[6];
    const float* kbi   = (const float*)d_in[7];
    const float* tab   = (const float*)d_in[8];
    const float* w_out = (const float*)d_in[9];
    const float* b_out = (const float*)d_in[10];
    float* y = (float*)d_out;

    cudaFuncSetAttribute(qkv_gemm_tc, cudaFuncAttributeMaxDynamicSharedMemorySize, SMEM_GEMM);
    cudaFuncSetAttribute(out_gemm_tc, cudaFuncAttributeMaxDynamicSharedMemorySize, SMEM_GEMM);

    gn_stats_kernel<<<T_*NH, 256>>>(x);
    prep_w_kernel<<<(N1*C_/4 + C_*C_/4)/256, 256>>>(w_in, w_out);
    prep_x_kernel<<<dim3(M_/64, C_/64), 256>>>(x, nw);
    qkv_gemm_tc<<<dim3(N1/128, M_/128), 128 + 128, SMEM_GEMM>>>(b_in);
    attn_kernel<<<SPA*NH, 128>>>(qsc, qbi, ksc, kbi, tab);
    out_gemm_tc<<<dim3(C_/128, M_/128), 256, SMEM_GEMM>>>(x, b_out, y);
}

// round 4
// speedup vs baseline: 2.1953x; 1.0801x over previous
#include <cuda_runtime.h>
#include <cuda_bf16.h>
#include <math.h>
#include <stdint.h>

#define T_   16
#define SPA  2048
#define C_   768
#define NH   12
#define HD   64
#define N1   2304
#define M_   (T_*SPA)   // 32768

// ---------------- scratch (static device allocations) ----------------------
__device__ float g_rstd[T_*NH];
__device__ float g_qkv[(size_t)SPA*NH*T_*192];
__device__ __nv_bfloat16 g_xh[(size_t)M_*C_], g_xl[(size_t)M_*C_];
__device__ __nv_bfloat16 g_wih[(size_t)N1*C_], g_wil[(size_t)N1*C_];
__device__ __nv_bfloat16 g_woh[(size_t)C_*C_], g_wol[(size_t)C_*C_];
__device__ __nv_bfloat16 g_oh[(size_t)M_*C_], g_ol[(size_t)M_*C_];

// ---------------- helpers ---------------------------------------------------
static __device__ __forceinline__ uint32_t smem_u32(const void* p) {
    uint32_t a;
    asm("{ .reg .u64 t; cvta.to.shared.u64 t, %1; cvt.u32.u64 %0, t; }" : "=r"(a) : "l"(p));
    return a;
}
static __device__ __forceinline__ unsigned pk2(float a, float b) {
    unsigned short ua = __bfloat16_as_ushort(__float2bfloat16(a));
    unsigned short ub = __bfloat16_as_ushort(__float2bfloat16(b));
    return (unsigned)ua | ((unsigned)ub << 16);
}
static __device__ __forceinline__ void split2(float a, float b, unsigned& hi, unsigned& lo) {
    __nv_bfloat16 ha = __float2bfloat16(a), hb = __float2bfloat16(b);
    hi = (unsigned)__bfloat16_as_ushort(ha) | ((unsigned)__bfloat16_as_ushort(hb) << 16);
    lo = pk2(a - __bfloat162float(ha), b - __bfloat162float(hb));
}

#define CP16(smem, gp) \
    asm volatile("cp.async.cg.shared.global [%0], [%1], 16;" :: "r"(smem), "l"(gp) : "memory")
#define CP_COMMIT() asm volatile("cp.async.commit_group;" ::: "memory")
#define CP_WAIT1()  asm volatile("cp.async.wait_group 1;" ::: "memory")
#define CP_WAIT0()  asm volatile("cp.async.wait_group 0;" ::: "memory")

#define LDSM4(r, addr) \
    asm volatile("ldmatrix.sync.aligned.m8n8.x4.shared.b16 {%0,%1,%2,%3}, [%4];" \
        : "=r"((r)[0]), "=r"((r)[1]), "=r"((r)[2]), "=r"((r)[3]) : "r"(addr))

#define MMA(d, a, b0, b1) \
    asm volatile("mma.sync.aligned.m16n8k16.row.col.f32.bf16.bf16.f32 " \
        "{%0,%1,%2,%3}, {%4,%5,%6,%7}, {%8,%9}, {%0,%1,%2,%3};" \
        : "+f"((d)[0]), "+f"((d)[1]), "+f"((d)[2]), "+f"((d)[3]) \
        : "r"((a)[0]), "r"((a)[1]), "r"((a)[2]), "r"((a)[3]), "r"(b0), "r"(b1))

#define NSTAGE 3
#define STAGE_BYTES 32768

// ---------------------------------------------------------------------------
// Kernel 1: RMS groupnorm stats
// ---------------------------------------------------------------------------
__global__ void gn_stats_kernel(const float* __restrict__ x) {
    int g = blockIdx.x % NH, t = blockIdx.x / NH;
    const float4* p = (const float4*)(x + (size_t)t*C_*SPA + (size_t)g*HD*SPA);
    float ss = 0.f;
    for (int i = threadIdx.x; i < (HD*SPA)/4; i += blockDim.x) {
        float4 v = p[i];
        ss += v.x*v.x + v.y*v.y + v.z*v.z + v.w*v.w;
    }
    __shared__ float red[256];
    red[threadIdx.x] = ss;
    __syncthreads();
    for (int o = 128; o > 0; o >>= 1) {
        if (threadIdx.x < o) red[threadIdx.x] += red[threadIdx.x + o];
        __syncthreads();
    }
    if (threadIdx.x == 0)
        g_rstd[t*NH + g] = rsqrtf(red[0] * (1.f/(HD*SPA)) + 1e-6f);
}

// ---------------------------------------------------------------------------
// Kernel 2: transpose + scale + bf16-split x -> g_xh/g_xl  [m=(t,s)][c]
// ---------------------------------------------------------------------------
__global__ void prep_x_kernel(const float* __restrict__ x, const float* __restrict__ nw) {
    __shared__ float tile[64][65];
    int bm = blockIdx.x * 64, c0 = blockIdx.y * 64;
    int t = bm >> 11, s0 = bm & (SPA-1);
    int tid = threadIdx.x;
    int sl = tid & 63, cb = tid >> 6;
    #pragma unroll
    for (int r = 0; r < 16; r++) {
        int c = cb*16 + r, cg = c0 + c;
        float sc = g_rstd[t*NH + (cg >> 6)] * nw[cg];
        tile[sl][c] = x[(size_t)t*C_*SPA + (size_t)cg*SPA + s0 + sl] * sc;
    }
    __syncthreads();
    int cl = tid & 31, mb = tid >> 5;
    #pragma unroll
    for (int r = 0; r < 8; r++) {
        int m = mb*8 + r;
        unsigned hi, lo;
        split2(tile[m][2*cl], tile[m][2*cl+1], hi, lo);
        size_t o = (size_t)(bm+m)*(C_/2) + (c0 >> 1) + cl;
        ((unsigned*)g_xh)[o] = hi;
        ((unsigned*)g_xl)[o] = lo;
    }
}

// ---------------------------------------------------------------------------
// Kernel 3: bf16-split both weight matrices
// ---------------------------------------------------------------------------
__global__ void prep_w_kernel(const float* __restrict__ win, const float* __restrict__ wout) {
    int i = blockIdx.x * 256 + threadIdx.x;
    const int NI = N1*C_/4;
    float4 v; unsigned* dh; unsigned* dl; int j;
    if (i < NI) { v = ((const float4*)win)[i]; dh = (unsigned*)g_wih; dl = (unsigned*)g_wil; j = i; }
    else        { j = i - NI; v = ((const float4*)wout)[j]; dh = (unsigned*)g_woh; dl = (unsigned*)g_wol; }
    unsigned h0, l0, h1, l1;
    split2(v.x, v.y, h0, l0);
    split2(v.z, v.w, h1, l1);
    dh[2*j] = h0; dh[2*j+1] = h1;
    dl[2*j] = l0; dl[2*j+1] = l1;
}

// ---------------------------------------------------------------------------
// MMA mainloop: CTA 128x128, K=768, k32 chunks as 128B rows [hi|lo], SW128,
// 3-stage cp.async pipeline. B fragments loaded transiently (reg pressure).
// ---------------------------------------------------------------------------
static __device__ __forceinline__ void stage_fill(uint32_t dst, const char* ap,
                                                  const char* bp, uint32_t xld, int hf) {
    #pragma unroll
    for (int i = 0; i < 4; i++) {
        uint32_t o = (uint32_t)((hf << 6) | (i << 4)) ^ xld;
        CP16(dst + o,         ap + i*16);
        CP16(dst + 16384 + o, bp + i*16);
    }
    CP_COMMIT();
}

static __device__ __forceinline__ void mma_mainloop(
        float acc[2][8][4], const char* aSrc, const char* bSrc, uint32_t sb) {
    int tid = threadIdx.x;
    int lid = tid & 31, wid = tid >> 5;
    int wm = (wid & 3) * 32, wn = (wid >> 2) * 64;
    int r  = tid >> 1, hf = tid & 1;

    uint32_t stRow = (uint32_t)(r * 128);
    uint32_t xld   = (uint32_t)((r & 7) << 4);

    uint32_t xr   = (uint32_t)((lid & 7) << 4);
    uint32_t aSel = (uint32_t)(((lid >> 4) & 1) << 4);
    uint32_t bSel = (uint32_t)(((lid >> 3) & 1) << 4);
    uint32_t arb[2], brb[4];
    #pragma unroll
    for (int mt = 0; mt < 2; mt++)
        arb[mt] = (uint32_t)((wm + mt*16 + (lid & 15)) * 128);
    #pragma unroll
    for (int nt = 0; nt < 4; nt++)
        brb[nt] = (uint32_t)((wn + nt*16 + (lid & 7) + (((lid >> 4) & 1) << 3)) * 128);

    // prologue: stages 0 and 1
    stage_fill(sb + stRow, aSrc, bSrc, xld, hf);
    stage_fill(sb + STAGE_BYTES + stRow, aSrc + 64, bSrc + 64, xld, hf);

    uint32_t stage = 0;
    for (int c = 0; c < 24; c++) {
        if (c < 23) CP_WAIT1(); else CP_WAIT0();
        __syncthreads();
        if (c + 2 < 24) {
            uint32_t nst = stage + 2; if (nst >= NSTAGE) nst -= NSTAGE;
            stage_fill(sb + nst*STAGE_BYTES + stRow,
                       aSrc + (size_t)(c+2)*64, bSrc + (size_t)(c+2)*64, xld, hf);
        }
        uint32_t bo = stage * STAGE_BYTES;
        #pragma unroll
        for (int kk = 0; kk < 2; kk++) {
            uint32_t cb = (uint32_t)(kk << 5);
            uint32_t ah[2][4], al[2][4];
            #pragma unroll
            for (int mt = 0; mt < 2; mt++) {
                uint32_t base = sb + bo + arb[mt];
                LDSM4(ah[mt], base + ((cb | aSel) ^ xr));
                LDSM4(al[mt], base + (((1u<<6) | cb | aSel) ^ xr));
            }
            #pragma unroll
            for (int nt = 0; nt < 4; nt++) {
                uint32_t base = sb + bo + 16384 + brb[nt];
                uint32_t bh[4], bl[4];
                LDSM4(bh, base + ((cb | bSel) ^ xr));
                LDSM4(bl, base + (((1u<<6) | cb | bSel) ^ xr));
                #pragma unroll
                for (int n8 = 0; n8 < 2; n8++) {
                    #pragma unroll
                    for (int mt = 0; mt < 2; mt++) {
                        MMA(acc[mt][nt*2+n8], ah[mt], bh[n8*2], bh[n8*2+1]);
                        MMA(acc[mt][nt*2+n8], ah[mt], bl[n8*2], bl[n8*2+1]);
                        MMA(acc[mt][nt*2+n8], al[mt], bh[n8*2], bh[n8*2+1]);
                    }
                }
            }
        }
        __syncthreads();
        stage = stage + 1; if (stage >= NSTAGE) stage -= NSTAGE;
    }
}

// Stage accumulators into smem as [128][132] f32
static __device__ __forceinline__ void stage_acc(float acc[2][8][4], float* st) {
    int tid = threadIdx.x, lid = tid & 31, wid = tid >> 5;
    int wm = (wid & 3) * 32, wn = (wid >> 2) * 64;
    int qr = lid >> 2, qc = (lid & 3) * 2;
    #pragma unroll
    for (int mt = 0; mt < 2; mt++)
        #pragma unroll
        for (int n8 = 0; n8 < 8; n8++) {
            float* p0 = st + (wm + mt*16 + qr)*132 + wn + n8*8 + qc;
            p0[0] = acc[mt][n8][0];
            p0[1] = acc[mt][n8][1];
            p0[8*132]   = acc[mt][n8][2];
            p0[8*132+1] = acc[mt][n8][3];
        }
}

// ---------------------------------------------------------------------------
// Kernel 4: QKV GEMM
// ---------------------------------------------------------------------------
__global__ void __launch_bounds__(256, 2) qkv_gemm_tc(const float* __restrict__ bias) {
    extern __shared__ char smem[];
    uint32_t sb = smem_u32(smem);
    int tid = threadIdx.x;
    int bn = blockIdx.x * 128, bm = blockIdx.y * 128;
    int r = tid >> 1, hf = tid & 1;
    const char* aSrc = (const char*)((hf ? g_xl  : g_xh ) + (size_t)(bm + r)*C_);
    const char* bSrc = (const char*)((hf ? g_wil : g_wih) + (size_t)(bn + r)*C_);

    float acc[2][8][4] = {};
    mma_mainloop(acc, aSrc, bSrc, sb);
    __syncthreads();
    float* st = (float*)smem;
    stage_acc(acc, st);
    __syncthreads();

    int t = bm >> 11, s = (bm & (SPA-1)) + (tid >> 1);
    int n0 = bn + (tid & 1) * 64;
    int h = n0 / 192, j0 = n0 % 192;
    float* dst = &g_qkv[(((size_t)s*NH + h)*T_ + t)*192 + j0];
    const float* src = st + (tid >> 1)*132 + (tid & 1)*64;
    #pragma unroll
    for (int i = 0; i < 16; i++) {
        float4 v  = *(const float4*)(src + i*4);
        float4 bv = *(const float4*)(bias + n0 + i*4);
        v.x += bv.x; v.y += bv.y; v.z += bv.z; v.w += bv.w;
        *(float4*)(dst + i*4) = v;
    }
}

// ---------------------------------------------------------------------------
// Kernel 5: attention
// ---------------------------------------------------------------------------
__global__ void attn_kernel(const float* __restrict__ qsc, const float* __restrict__ qbi,
                            const float* __restrict__ ksc, const float* __restrict__ kbi,
                            const float* __restrict__ tab) {
    int sh = blockIdx.x;
    int h = sh % NH, s = sh / NH;
    __shared__ float qs[16][65], ks[16][65], vs[16][65], P[16][17];
    int tid = threadIdx.x;
    int row = tid >> 3, part = tid & 7;
    const float* base = g_qkv + (size_t)sh*(T_*192) + row*192 + part*8;

    {
        float v0[8];
        #pragma unroll
        for (int e = 0; e < 8; e++) v0[e] = base[e];
        float sum = 0.f;
        #pragma unroll
        for (int e = 0; e < 8; e++) sum += v0[e];
        sum += __shfl_xor_sync(~0u, sum, 1); sum += __shfl_xor_sync(~0u, sum, 2); sum += __shfl_xor_sync(~0u, sum, 4);
        float mu = sum * (1.f/64.f), var = 0.f;
        #pragma unroll
        for (int e = 0; e < 8; e++) { float d = v0[e]-mu; var += d*d; }
        var += __shfl_xor_sync(~0u, var, 1); var += __shfl_xor_sync(~0u, var, 2); var += __shfl_xor_sync(~0u, var, 4);
        float rr = rsqrtf(var * (1.f/64.f) + 1e-6f);
        #pragma unroll
        for (int e = 0; e < 8; e++) { int j = part*8+e; qs[row][j] = (v0[e]-mu)*rr*qsc[j] + qbi[j]; }
    }
    {
        float v0[8];
        #pragma unroll
        for (int e = 0; e < 8; e++) v0[e] = base[64+e];
        float sum = 0.f;
        #pragma unroll
        for (int e = 0; e < 8; e++) sum += v0[e];
        sum += __shfl_xor_sync(~0u, sum, 1); sum += __shfl_xor_sync(~0u, sum, 2); sum += __shfl_xor_sync(~0u, sum, 4);
        float mu = sum * (1.f/64.f), var = 0.f;
        #pragma unroll
        for (int e = 0; e < 8; e++) { float d = v0[e]-mu; var += d*d; }
        var += __shfl_xor_sync(~0u, var, 1); var += __shfl_xor_sync(~0u, var, 2); var += __shfl_xor_sync(~0u, var, 4);
        float rr = rsqrtf(var * (1.f/64.f) + 1e-6f);
        #pragma unroll
        for (int e = 0; e < 8; e++) { int j = part*8+e; ks[row][j] = (v0[e]-mu)*rr*ksc[j] + kbi[j]; }
    }
    #pragma unroll
    for (int e = 0; e < 8; e++) vs[row][part*8+e] = base[128+e];
    __syncthreads();

    const float inv_log16_x8 = 8.f / logf(16.f);
    for (int e = tid; e < 256; e += 128) {
        int i = e >> 4, j = e & 15;
        float d = 0.f;
        #pragma unroll
        for (int c = 0; c < 64; c++) d += qs[i][c]*ks[j][c];
        int rp = j - i;
        int ret = (rp > 0) ? 16 : 0;
        int n = rp < 0 ? -rp : rp;
        int bkt;
        if (n < 8) bkt = ret + n;
        else {
            int vl = 8 + (int)(logf((float)n * 0.125f) * inv_log16_x8);
            bkt = ret + (vl < 15 ? vl : 15);
        }
        P[i][j] = d * 0.125f + tab[bkt*NH + h];
    }
    __syncthreads();
    if (tid < 16) {
        float m = -1e30f;
        #pragma unroll
        for (int j = 0; j < 16; j++) m = fmaxf(m, P[tid][j]);
        float sum = 0.f;
        #pragma unroll
        for (int j = 0; j < 16; j++) { float e = expf(P[tid][j]-m); P[tid][j] = e; sum += e; }
        float inv = 1.f / sum;
        #pragma unroll
        for (int j = 0; j < 16; j++) P[tid][j] *= inv;
    }
    __syncthreads();

    float o[8] = {0,0,0,0,0,0,0,0};
    #pragma unroll
    for (int t2 = 0; t2 < 16; t2++) {
        float p = P[row][t2];
        #pragma unroll
        for (int e = 0; e < 8; e++) o[e] += p * vs[t2][part*8+e];
    }
    unsigned H[4], L[4];
    #pragma unroll
    for (int e = 0; e < 4; e++) split2(o[2*e], o[2*e+1], H[e], L[e]);
    size_t off = ((size_t)row*SPA + s)*C_ + h*HD + part*8;
    *(uint4*)(g_oh + off) = make_uint4(H[0], H[1], H[2], H[3]);
    *(uint4*)(g_ol + off) = make_uint4(L[0], L[1], L[2], L[3]);
}

// ---------------------------------------------------------------------------
// Kernel 6: output GEMM + bias + residual
// ---------------------------------------------------------------------------
__global__ void __launch_bounds__(256, 2) out_gemm_tc(const float* __restrict__ x,
                                                      const float* __restrict__ bias,
                                                      float* __restrict__ y) {
    extern __shared__ char smem[];
    uint32_t sb = smem_u32(smem);
    int tid = threadIdx.x;
    int bn = blockIdx.x * 128, bm = blockIdx.y * 128;
    int r = tid >> 1, hf = tid & 1;
    const char* aSrc = (const char*)((hf ? g_ol  : g_oh ) + (size_t)(bm + r)*C_);
    const char* bSrc = (const char*)((hf ? g_wol : g_woh) + (size_t)(bn + r)*C_);

    float acc[2][8][4] = {};
    mma_mainloop(acc, aSrc, bSrc, sb);
    __syncthreads();
    float* st = (float*)smem;
    stage_acc(acc, st);
    __syncthreads();

    int n = bn + (tid >> 1);
    int sh_ = tid & 1;
    int t = bm >> 11, s0 = bm & (SPA-1);
    size_t off = (size_t)t*C_*SPA + (size_t)n*SPA + s0 + sh_*64;
    float bb = bias[n];
    const float* src = st + sh_*64*132 + (n - bn);
    #pragma unroll
    for (int i = 0; i < 64; i += 4) {
        float4 rx = *(const float4*)(x + off + i);
        float4 v = make_float4(src[(i+0)*132], src[(i+1)*132],
                               src[(i+2)*132], src[(i+3)*132]);
        v.x += bb + rx.x; v.y += bb + rx.y; v.z += bb + rx.z; v.w += bb + rx.w;
        *(float4*)(y + off + i) = v;
    }
}

// ---------------------------------------------------------------------------
#define SMEM_GEMM (NSTAGE*STAGE_BYTES)   // 98304

extern "C" void kernel_launch(void* const* d_in, const int* in_sizes, int n_in,
                              void* d_out, int out_size) {
    const float* x     = (const float*)d_in[0];
    const float* nw    = (const float*)d_in[1];
    const float* w_in  = (const float*)d_in[2];
    const float* b_in  = (const float*)d_in[3];
    const float* qsc   = (const float*)d_in[4];
    const float* qbi   = (const float*)d_in[5];
    const float* ksc   = (const float*)d_in[6];
    const float* kbi   = (const float*)d_in[7];
    const float* tab   = (const float*)d_in[8];
    const float* w_out = (const float*)d_in[9];
    const float* b_out = (const float*)d_in[10];
    float* y = (float*)d_out;

    cudaFuncSetAttribute(qkv_gemm_tc, cudaFuncAttributeMaxDynamicSharedMemorySize, SMEM_GEMM);
    cudaFuncSetAttribute(out_gemm_tc, cudaFuncAttributeMaxDynamicSharedMemorySize, SMEM_GEMM);

    gn_stats_kernel<<<T_*NH, 256>>>(x);
    prep_w_kernel<<<(N1*C_/4 + C_*C_/4)/256, 256>>>(w_in, w_out);
    prep_x_kernel<<<dim3(M_/64, C_/64), 256>>>(x, nw);
    qkv_gemm_tc<<<dim3(N1/128, M_/128), 256, SMEM_GEMM>>>(b_in);
    attn_kernel<<<SPA*NH, 128>>>(qsc, qbi, ksc, kbi, tab);
    out_gemm_tc<<<dim3(C_/128, M_/128), 256, SMEM_GEMM>>>(x, b_out, y);
}

// round 6
// speedup vs baseline: 3.5035x; 1.5959x over previous
#include <cuda_runtime.h>
#include <cuda_bf16.h>
#include <cuda_fp16.h>
#include <math.h>
#include <stdint.h>

#define T_   16
#define SPA  2048
#define C_   768
#define NH   12
#define HD   64
#define N1   2304
#define M_   (T_*SPA)   // 32768

// ---------------- scratch (static device allocations) ----------------------
__device__ float g_rstd[T_*NH];
__device__ float g_qkv[(size_t)SPA*NH*T_*192];
__device__ __half g_ah[(size_t)M_*C_];                    // A for qkv GEMM (fp16)
__device__ __half g_wih[(size_t)N1*C_], g_wil[(size_t)N1*C_];
__device__ __half g_woh[(size_t)C_*C_], g_wol[(size_t)C_*C_];
__device__ __half g_oh[(size_t)M_*C_];                    // attn out (fp16)

// ---------------- helpers ---------------------------------------------------
static __device__ __forceinline__ uint32_t smem_u32(const void* p) {
    uint32_t a;
    asm("{ .reg .u64 t; cvta.to.shared.u64 t, %1; cvt.u32.u64 %0, t; }" : "=r"(a) : "l"(p));
    return a;
}

#define CP16(smem, gp) \
    asm volatile("cp.async.cg.shared.global [%0], [%1], 16;" :: "r"(smem), "l"(gp) : "memory")
#define CP_COMMIT() asm volatile("cp.async.commit_group;" ::: "memory")
#define CP_WAIT1()  asm volatile("cp.async.wait_group 1;" ::: "memory")
#define CP_WAIT0()  asm volatile("cp.async.wait_group 0;" ::: "memory")

#define LDSM4(r, addr) \
    asm volatile("ldmatrix.sync.aligned.m8n8.x4.shared.b16 {%0,%1,%2,%3}, [%4];" \
        : "=r"((r)[0]), "=r"((r)[1]), "=r"((r)[2]), "=r"((r)[3]) : "r"(addr))

#define MMAH(d, a, b0, b1) \
    asm volatile("mma.sync.aligned.m16n8k16.row.col.f32.f16.f16.f32 " \
        "{%0,%1,%2,%3}, {%4,%5,%6,%7}, {%8,%9}, {%0,%1,%2,%3};" \
        : "+f"((d)[0]), "+f"((d)[1]), "+f"((d)[2]), "+f"((d)[3]) \
        : "r"((a)[0]), "r"((a)[1]), "r"((a)[2]), "r"((a)[3]), "r"(b0), "r"(b1))

#define STAGE_BYTES 49152   // A 16KB | Bh 16KB | Bl 16KB  (k64 chunk)
#define SMEM_GEMM   (2*STAGE_BYTES)   // 96KB

// ---------------------------------------------------------------------------
// Kernel 1: RMS groupnorm stats
// ---------------------------------------------------------------------------
__global__ void gn_stats_kernel(const float* __restrict__ x) {
    int g = blockIdx.x % NH, t = blockIdx.x / NH;
    const float4* p = (const float4*)(x + (size_t)t*C_*SPA + (size_t)g*HD*SPA);
    float ss = 0.f;
    for (int i = threadIdx.x; i < (HD*SPA)/4; i += blockDim.x) {
        float4 v = p[i];
        ss += v.x*v.x + v.y*v.y + v.z*v.z + v.w*v.w;
    }
    __shared__ float red[256];
    red[threadIdx.x] = ss;
    __syncthreads();
    for (int o = 128; o > 0; o >>= 1) {
        if (threadIdx.x < o) red[threadIdx.x] += red[threadIdx.x + o];
        __syncthreads();
    }
    if (threadIdx.x == 0)
        g_rstd[t*NH + g] = rsqrtf(red[0] * (1.f/(HD*SPA)) + 1e-6f);
}

// ---------------------------------------------------------------------------
// Kernel 2: transpose + scale + fp16 x -> g_ah  [m=(t,s)][c]
// ---------------------------------------------------------------------------
__global__ void prep_x_kernel(const float* __restrict__ x, const float* __restrict__ nw) {
    __shared__ float tile[64][65];
    int bm = blockIdx.x * 64, c0 = blockIdx.y * 64;
    int t = bm >> 11, s0 = bm & (SPA-1);
    int tid = threadIdx.x;
    int sl = tid & 63, cb = tid >> 6;
    #pragma unroll
    for (int r = 0; r < 16; r++) {
        int c = cb*16 + r, cg = c0 + c;
        float sc = g_rstd[t*NH + (cg >> 6)] * nw[cg];
        tile[sl][c] = x[(size_t)t*C_*SPA + (size_t)cg*SPA + s0 + sl] * sc;
    }
    __syncthreads();
    int cl = tid & 31, mb = tid >> 5;
    #pragma unroll
    for (int r = 0; r < 8; r++) {
        int m = mb*8 + r;
        __half2 h = __floats2half2_rn(tile[m][2*cl], tile[m][2*cl+1]);
        ((__half2*)g_ah)[(size_t)(bm+m)*(C_/2) + (c0 >> 1) + cl] = h;
    }
}

// ---------------------------------------------------------------------------
// Kernel 3: fp16 hi/lo split of both weight matrices
// ---------------------------------------------------------------------------
static __device__ __forceinline__ void split2h(float a, float b, unsigned& hi, unsigned& lo) {
    __half ha = __float2half_rn(a), hb = __float2half_rn(b);
    __half la = __float2half_rn(a - __half2float(ha));
    __half lb = __float2half_rn(b - __half2float(hb));
    hi = (unsigned)__half_as_ushort(ha) | ((unsigned)__half_as_ushort(hb) << 16);
    lo = (unsigned)__half_as_ushort(la) | ((unsigned)__half_as_ushort(lb) << 16);
}
__global__ void prep_w_kernel(const float* __restrict__ win, const float* __restrict__ wout) {
    int i = blockIdx.x * 256 + threadIdx.x;
    const int NI = N1*C_/4;
    float4 v; unsigned* dh; unsigned* dl; int j;
    if (i < NI) { v = ((const float4*)win)[i]; dh = (unsigned*)g_wih; dl = (unsigned*)g_wil; j = i; }
    else        { j = i - NI; v = ((const float4*)wout)[j]; dh = (unsigned*)g_woh; dl = (unsigned*)g_wol; }
    unsigned h0, l0, h1, l1;
    split2h(v.x, v.y, h0, l0);
    split2h(v.z, v.w, h1, l1);
    dh[2*j] = h0; dh[2*j+1] = h1;
    dl[2*j] = l0; dl[2*j+1] = l1;
}

// ---------------------------------------------------------------------------
// MMA mainloop: CTA 128x128, K=768 as 12 k64 chunks, 2-stage cp.async.
// Stage: A(128x128B) | Bh(128x128B) | Bl(128x128B), SW128 swizzle.
// D = A*Bh + A*Bl, fp16 operands, fp32 accum.
// ---------------------------------------------------------------------------
static __device__ __forceinline__ void mma_mainloop(
        float acc[2][8][4], const char* aSrc, const char* bhSrc, const char* blSrc,
        uint32_t sb) {
    int tid = threadIdx.x;
    int lid = tid & 31, wid = tid >> 5;
    int wm = (wid & 3) * 32, wn = (wid >> 2) * 64;
    int r  = tid >> 1, part = tid & 1;

    uint32_t stRow = (uint32_t)(r * 128);
    uint32_t xld   = (uint32_t)((r & 7) << 4);
    uint32_t xr    = (uint32_t)((lid & 7) << 4);
    uint32_t aSel  = (uint32_t)(((lid >> 4) & 1) << 4);
    uint32_t bSel  = (uint32_t)(((lid >> 3) & 1) << 4);
    uint32_t arb[2], brb[4];
    #pragma unroll
    for (int mt = 0; mt < 2; mt++)
        arb[mt] = (uint32_t)((wm + mt*16 + (lid & 15)) * 128);
    #pragma unroll
    for (int nt = 0; nt < 4; nt++)
        brb[nt] = (uint32_t)((wn + nt*16 + (lid & 7) + (((lid >> 4) & 1) << 3)) * 128);

    // prologue: fill stage 0 with chunk 0
    {
        uint32_t dst = sb + stRow;
        #pragma unroll
        for (int i = 0; i < 4; i++) {
            uint32_t o = (uint32_t)((part << 6) | (i << 4)) ^ xld;
            CP16(dst + o,         aSrc  + i*16);
            CP16(dst + 16384 + o, bhSrc + i*16);
            CP16(dst + 32768 + o, blSrc + i*16);
        }
        CP_COMMIT();
    }

    for (int c = 0; c < 12; c++) {
        if (c + 1 < 12) {
            uint32_t dst = sb + (uint32_t)(((c+1) & 1) * STAGE_BYTES) + stRow;
            const char* ap  = aSrc  + (size_t)(c+1)*128;
            const char* bhp = bhSrc + (size_t)(c+1)*128;
            const char* blp = blSrc + (size_t)(c+1)*128;
            #pragma unroll
            for (int i = 0; i < 4; i++) {
                uint32_t o = (uint32_t)((part << 6) | (i << 4)) ^ xld;
                CP16(dst + o,         ap  + i*16);
                CP16(dst + 16384 + o, bhp + i*16);
                CP16(dst + 32768 + o, blp + i*16);
            }
            CP_COMMIT();
            CP_WAIT1();
        } else {
            CP_WAIT0();
        }
        __syncthreads();
        uint32_t bo = (uint32_t)((c & 1) * STAGE_BYTES);
        #pragma unroll
        for (int kk = 0; kk < 4; kk++) {
            uint32_t cb = (uint32_t)(kk << 5);
            uint32_t ah[2][4];
            #pragma unroll
            for (int mt = 0; mt < 2; mt++)
                LDSM4(ah[mt], sb + bo + arb[mt] + ((cb | aSel) ^ xr));
            #pragma unroll
            for (int nt = 0; nt < 4; nt++) {
                uint32_t bh[4], bl[4];
                LDSM4(bh, sb + bo + 16384 + brb[nt] + ((cb | bSel) ^ xr));
                LDSM4(bl, sb + bo + 32768 + brb[nt] + ((cb | bSel) ^ xr));
                #pragma unroll
                for (int n8 = 0; n8 < 2; n8++) {
                    #pragma unroll
                    for (int mt = 0; mt < 2; mt++) {
                        MMAH(acc[mt][nt*2+n8], ah[mt], bh[n8*2], bh[n8*2+1]);
                        MMAH(acc[mt][nt*2+n8], ah[mt], bl[n8*2], bl[n8*2+1]);
                    }
                }
            }
        }
        __syncthreads();
    }
}

// Stage accumulators into smem as [128][132] f32
static __device__ __forceinline__ void stage_acc(float acc[2][8][4], float* st) {
    int tid = threadIdx.x, lid = tid & 31, wid = tid >> 5;
    int wm = (wid & 3) * 32, wn = (wid >> 2) * 64;
    int qr = lid >> 2, qc = (lid & 3) * 2;
    #pragma unroll
    for (int mt = 0; mt < 2; mt++)
        #pragma unroll
        for (int n8 = 0; n8 < 8; n8++) {
            float* p0 = st + (wm + mt*16 + qr)*132 + wn + n8*8 + qc;
            p0[0] = acc[mt][n8][0];
            p0[1] = acc[mt][n8][1];
            p0[8*132]   = acc[mt][n8][2];
            p0[8*132+1] = acc[mt][n8][3];
        }
}

// ---------------------------------------------------------------------------
// Kernel 4: QKV GEMM
// ---------------------------------------------------------------------------
__global__ void __launch_bounds__(256, 2) qkv_gemm_tc(const float* __restrict__ bias) {
    extern __shared__ char smem[];
    uint32_t sb = smem_u32(smem);
    int tid = threadIdx.x;
    int bn = blockIdx.x * 128, bm = blockIdx.y * 128;
    int r = tid >> 1, part = tid & 1;
    const char* aSrc  = (const char*)(g_ah  + (size_t)(bm + r)*C_) + part*64;
    const char* bhSrc = (const char*)(g_wih + (size_t)(bn + r)*C_) + part*64;
    const char* blSrc = (const char*)(g_wil + (size_t)(bn + r)*C_) + part*64;

    float acc[2][8][4] = {};
    mma_mainloop(acc, aSrc, bhSrc, blSrc, sb);
    __syncthreads();
    float* st = (float*)smem;
    stage_acc(acc, st);
    __syncthreads();

    int t = bm >> 11, s = (bm & (SPA-1)) + (tid >> 1);
    int n0 = bn + (tid & 1) * 64;
    int h = n0 / 192, j0 = n0 % 192;
    float* dst = &g_qkv[(((size_t)s*NH + h)*T_ + t)*192 + j0];
    const float* src = st + (tid >> 1)*132 + (tid & 1)*64;
    #pragma unroll
    for (int i = 0; i < 16; i++) {
        float4 v  = *(const float4*)(src + i*4);
        float4 bv = *(const float4*)(bias + n0 + i*4);
        v.x += bv.x; v.y += bv.y; v.z += bv.z; v.w += bv.w;
        *(float4*)(dst + i*4) = v;
    }
}

// ---------------------------------------------------------------------------
// Kernel 5: attention (fp32), writes fp16 output for out GEMM
// ---------------------------------------------------------------------------
__global__ void attn_kernel(const float* __restrict__ qsc, const float* __restrict__ qbi,
                            const float* __restrict__ ksc, const float* __restrict__ kbi,
                            const float* __restrict__ tab) {
    int sh = blockIdx.x;
    int h = sh % NH, s = sh / NH;
    __shared__ float qs[16][65], ks[16][65], vs[16][65], P[16][17];
    int tid = threadIdx.x;
    int row = tid >> 3, part = tid & 7;
    const float* base = g_qkv + (size_t)sh*(T_*192) + row*192 + part*8;

    {
        float v0[8];
        #pragma unroll
        for (int e = 0; e < 8; e++) v0[e] = base[e];
        float sum = 0.f;
        #pragma unroll
        for (int e = 0; e < 8; e++) sum += v0[e];
        sum += __shfl_xor_sync(~0u, sum, 1); sum += __shfl_xor_sync(~0u, sum, 2); sum += __shfl_xor_sync(~0u, sum, 4);
        float mu = sum * (1.f/64.f), var = 0.f;
        #pragma unroll
        for (int e = 0; e < 8; e++) { float d = v0[e]-mu; var += d*d; }
        var += __shfl_xor_sync(~0u, var, 1); var += __shfl_xor_sync(~0u, var, 2); var += __shfl_xor_sync(~0u, var, 4);
        float rr = rsqrtf(var * (1.f/64.f) + 1e-6f);
        #pragma unroll
        for (int e = 0; e < 8; e++) { int j = part*8+e; qs[row][j] = (v0[e]-mu)*rr*qsc[j] + qbi[j]; }
    }
    {
        float v0[8];
        #pragma unroll
        for (int e = 0; e < 8; e++) v0[e] = base[64+e];
        float sum = 0.f;
        #pragma unroll
        for (int e = 0; e < 8; e++) sum += v0[e];
        sum += __shfl_xor_sync(~0u, sum, 1); sum += __shfl_xor_sync(~0u, sum, 2); sum += __shfl_xor_sync(~0u, sum, 4);
        float mu = sum * (1.f/64.f), var = 0.f;
        #pragma unroll
        for (int e = 0; e < 8; e++) { float d = v0[e]-mu; var += d*d; }
        var += __shfl_xor_sync(~0u, var, 1); var += __shfl_xor_sync(~0u, var, 2); var += __shfl_xor_sync(~0u, var, 4);
        float rr = rsqrtf(var * (1.f/64.f) + 1e-6f);
        #pragma unroll
        for (int e = 0; e < 8; e++) { int j = part*8+e; ks[row][j] = (v0[e]-mu)*rr*ksc[j] + kbi[j]; }
    }
    #pragma unroll
    for (int e = 0; e < 8; e++) vs[row][part*8+e] = base[128+e];
    __syncthreads();

    const float inv_log16_x8 = 8.f / logf(16.f);
    for (int e = tid; e < 256; e += 128) {
        int i = e >> 4, j = e & 15;
        float d = 0.f;
        #pragma unroll
        for (int c = 0; c < 64; c++) d += qs[i][c]*ks[j][c];
        int rp = j - i;
        int ret = (rp > 0) ? 16 : 0;
        int n = rp < 0 ? -rp : rp;
        int bkt;
        if (n < 8) bkt = ret + n;
        else {
            int vl = 8 + (int)(logf((float)n * 0.125f) * inv_log16_x8);
            bkt = ret + (vl < 15 ? vl : 15);
        }
        P[i][j] = d * 0.125f + tab[bkt*NH + h];
    }
    __syncthreads();
    if (tid < 16) {
        float m = -1e30f;
        #pragma unroll
        for (int j = 0; j < 16; j++) m = fmaxf(m, P[tid][j]);
        float sum = 0.f;
        #pragma unroll
        for (int j = 0; j < 16; j++) { float e = expf(P[tid][j]-m); P[tid][j] = e; sum += e; }
        float inv = 1.f / sum;
        #pragma unroll
        for (int j = 0; j < 16; j++) P[tid][j] *= inv;
    }
    __syncthreads();

    float o[8] = {0,0,0,0,0,0,0,0};
    #pragma unroll
    for (int t2 = 0; t2 < 16; t2++) {
        float p = P[row][t2];
        #pragma unroll
        for (int e = 0; e < 8; e++) o[e] += p * vs[t2][part*8+e];
    }
    unsigned H[4];
    #pragma unroll
    for (int e = 0; e < 4; e++) {
        __half2 hh = __floats2half2_rn(o[2*e], o[2*e+1]);
        H[e] = *(unsigned*)&hh;
    }
    size_t off = ((size_t)row*SPA + s)*C_ + h*HD + part*8;
    *(uint4*)(g_oh + off) = make_uint4(H[0], H[1], H[2], H[3]);
}

// ---------------------------------------------------------------------------
// Kernel 6: output GEMM + bias + residual
// ---------------------------------------------------------------------------
__global__ void __launch_bounds__(256, 2) out_gemm_tc(const float* __restrict__ x,
                                                      const float* __restrict__ bias,
                                                      float* __restrict__ y) {
    extern __shared__ char smem[];
    uint32_t sb = smem_u32(smem);
    int tid = threadIdx.x;
    int bn = blockIdx.x * 128, bm = blockIdx.y * 128;
    int r = tid >> 1, part = tid & 1;
    const char* aSrc  = (const char*)(g_oh  + (size_t)(bm + r)*C_) + part*64;
    const char* bhSrc = (const char*)(g_woh + (size_t)(bn + r)*C_) + part*64;
    const char* blSrc = (const char*)(g_wol + (size_t)(bn + r)*C_) + part*64;

    float acc[2][8][4] = {};
    mma_mainloop(acc, aSrc, bhSrc, blSrc, sb);
    __syncthreads();
    float* st = (float*)smem;
    stage_acc(acc, st);
    __syncthreads();

    int n = bn + (tid >> 1);
    int sh_ = tid & 1;
    int t = bm >> 11, s0 = bm & (SPA-1);
    size_t off = (size_t)t*C_*SPA + (size_t)n*SPA + s0 + sh_*64;
    float bb = bias[n];
    const float* src = st + sh_*64*132 + (n - bn);
    #pragma unroll
    for (int i = 0; i < 64; i += 4) {
        float4 rx = *(const float4*)(x + off + i);
        float4 v = make_float4(src[(i+0)*132], src[(i+1)*132],
                               src[(i+2)*132], src[(i+3)*132]);
        v.x += bb + rx.x; v.y += bb + rx.y; v.z += bb + rx.z; v.w += bb + rx.w;
        *(float4*)(y + off + i) = v;
    }
}

// ---------------------------------------------------------------------------
extern "C" void kernel_launch(void* const* d_in, const int* in_sizes, int n_in,
                              void* d_out, int out_size) {
    const float* x     = (const float*)d_in[0];
    const float* nw    = (const float*)d_in[1];
    const float* w_in  = (const float*)d_in[2];
    const float* b_in  = (const float*)d_in[3];
    const float* qsc   = (const float*)d_in[4];
    const float* qbi   = (const float*)d_in[5];
    const float* ksc   = (const float*)d_in[6];
    const float* kbi   = (const float*)d_in[7];
    const float* tab   = (const float*)d_in[8];
    const float* w_out = (const float*)d_in[9];
    const float* b_out = (const float*)d_in[10];
    float* y = (float*)d_out;

    cudaFuncSetAttribute(qkv_gemm_tc, cudaFuncAttributeMaxDynamicSharedMemorySize, SMEM_GEMM);
    cudaFuncSetAttribute(out_gemm_tc, cudaFuncAttributeMaxDynamicSharedMemorySize, SMEM_GEMM);

    gn_stats_kernel<<<T_*NH, 256>>>(x);
    prep_w_kernel<<<(N1*C_/4 + C_*C_/4)/256, 256>>>(w_in, w_out);
    prep_x_kernel<<<dim3(M_/64, C_/64), 256>>>(x, nw);
    qkv_gemm_tc<<<dim3(N1/128, M_/128), 256, SMEM_GEMM>>>(b_in);
    attn_kernel<<<SPA*NH, 128>>>(qsc, qbi, ksc, kbi, tab);
    out_gemm_tc<<<dim3(C_/128, M_/128), 256, SMEM_GEMM>>>(x, b_out, y);
}

// round 9
// speedup vs baseline: 4.7994x; 1.3699x over previous
#include <cuda_runtime.h>
#include <cuda_fp16.h>
#include <math.h>
#include <stdint.h>

#define T_   16
#define SPA  2048
#define C_   768
#define NH   12
#define HD   64
#define N1   2304
#define M_   (T_*SPA)   // 32768

// ---------------- scratch (static device allocations) ----------------------
__device__ float g_rstd[T_*NH];
__device__ float g_qkv[(size_t)SPA*NH*T_*192];
__device__ __half g_ah[(size_t)M_*C_];          // A for qkv GEMM (fp16)
__device__ __half g_wih[(size_t)N1*C_];         // W_in fp16
__device__ __half g_woh[(size_t)C_*C_];         // W_out fp16
__device__ __half g_oh[(size_t)M_*C_];          // attn out (fp16)

// ---------------- helpers ---------------------------------------------------
static __device__ __forceinline__ uint32_t smem_u32(const void* p) {
    uint32_t a;
    asm("{ .reg .u64 t; cvta.to.shared.u64 t, %1; cvt.u32.u64 %0, t; }" : "=r"(a) : "l"(p));
    return a;
}

#define CP16(smem, gp) \
    asm volatile("cp.async.cg.shared.global [%0], [%1], 16;" :: "r"(smem), "l"(gp) : "memory")
#define CP_COMMIT() asm volatile("cp.async.commit_group;" ::: "memory")
#define CP_WAIT0()  asm volatile("cp.async.wait_group 0;" ::: "memory")

#define LDSM4(r, addr) \
    asm volatile("ldmatrix.sync.aligned.m8n8.x4.shared.b16 {%0,%1,%2,%3}, [%4];" \
        : "=r"((r)[0]), "=r"((r)[1]), "=r"((r)[2]), "=r"((r)[3]) : "r"(addr))

#define MMAH(d, a, b0, b1) \
    asm volatile("mma.sync.aligned.m16n8k16.row.col.f32.f16.f16.f32 " \
        "{%0,%1,%2,%3}, {%4,%5,%6,%7}, {%8,%9}, {%0,%1,%2,%3};" \
        : "+f"((d)[0]), "+f"((d)[1]), "+f"((d)[2]), "+f"((d)[3]) \
        : "r"((a)[0]), "r"((a)[1]), "r"((a)[2]), "r"((a)[3]), "r"(b0), "r"(b1))

#define STAGE_BYTES 32768            // A 16KB | B 16KB  (k64 chunk)
#define SMEM_GEMM   67584            // max(2 stages = 64KB, epilogue 128*132*4 = 67584B)

// ---------------------------------------------------------------------------
// Kernel 1: RMS groupnorm stats
// ---------------------------------------------------------------------------
__global__ void gn_stats_kernel(const float* __restrict__ x) {
    int g = blockIdx.x % NH, t = blockIdx.x / NH;
    const float4* p = (const float4*)(x + (size_t)t*C_*SPA + (size_t)g*HD*SPA);
    float ss = 0.f;
    for (int i = threadIdx.x; i < (HD*SPA)/4; i += blockDim.x) {
        float4 v = p[i];
        ss += v.x*v.x + v.y*v.y + v.z*v.z + v.w*v.w;
    }
    __shared__ float red[256];
    red[threadIdx.x] = ss;
    __syncthreads();
    for (int o = 128; o > 0; o >>= 1) {
        if (threadIdx.x < o) red[threadIdx.x] += red[threadIdx.x + o];
        __syncthreads();
    }
    if (threadIdx.x == 0)
        g_rstd[t*NH + g] = rsqrtf(red[0] * (1.f/(HD*SPA)) + 1e-6f);
}

// ---------------------------------------------------------------------------
// Kernel 2: transpose + scale + fp16 x -> g_ah  [m=(t,s)][c]
// ---------------------------------------------------------------------------
__global__ void prep_x_kernel(const float* __restrict__ x, const float* __restrict__ nw) {
    __shared__ float tile[64][65];
    int bm = blockIdx.x * 64, c0 = blockIdx.y * 64;
    int t = bm >> 11, s0 = bm & (SPA-1);
    int tid = threadIdx.x;
    int sl = tid & 63, cb = tid >> 6;
    #pragma unroll
    for (int r = 0; r < 16; r++) {
        int c = cb*16 + r, cg = c0 + c;
        float sc = g_rstd[t*NH + (cg >> 6)] * nw[cg];
        tile[sl][c] = x[(size_t)t*C_*SPA + (size_t)cg*SPA + s0 + sl] * sc;
    }
    __syncthreads();
    int cl = tid & 31, mb = tid >> 5;
    #pragma unroll
    for (int r = 0; r < 8; r++) {
        int m = mb*8 + r;
        __half2 h = __floats2half2_rn(tile[m][2*cl], tile[m][2*cl+1]);
        ((__half2*)g_ah)[(size_t)(bm+m)*(C_/2) + (c0 >> 1) + cl] = h;
    }
}

// ---------------------------------------------------------------------------
// Kernel 3: fp16 conversion of both weight matrices
// ---------------------------------------------------------------------------
__global__ void prep_w_kernel(const float* __restrict__ win, const float* __restrict__ wout) {
    int i = blockIdx.x * 256 + threadIdx.x;
    const int NI = N1*C_/4;
    float4 v; unsigned* dh; int j;
    if (i < NI) { v = ((const float4*)win)[i]; dh = (unsigned*)g_wih; j = i; }
    else        { j = i - NI; v = ((const float4*)wout)[j]; dh = (unsigned*)g_woh; }
    __half2 h0 = __floats2half2_rn(v.x, v.y);
    __half2 h1 = __floats2half2_rn(v.z, v.w);
    dh[2*j]   = *(unsigned*)&h0;
    dh[2*j+1] = *(unsigned*)&h1;
}

// ---------------------------------------------------------------------------
// MMA mainloop: CTA 128x128, K=768 as 12 k64 chunks, 2-stage cp.async,
// ONE __syncthreads per chunk (wait -> sync -> prefetch -> mma).
// Stage: A(128x128B) | B(128x128B), SW128 swizzle. fp16 x fp16, fp32 accum.
// ---------------------------------------------------------------------------
static __device__ __forceinline__ void stage_fill(uint32_t dst, const char* ap,
                                                  const char* bp, uint32_t xld, int part) {
    #pragma unroll
    for (int i = 0; i < 4; i++) {
        uint32_t o = (uint32_t)((part << 6) | (i << 4)) ^ xld;
        CP16(dst + o,         ap + i*16);
        CP16(dst + 16384 + o, bp + i*16);
    }
    CP_COMMIT();
}

static __device__ __forceinline__ void mma_mainloop(
        float acc[2][8][4], const char* aSrc, const char* bSrc, uint32_t sb) {
    int tid = threadIdx.x;
    int lid = tid & 31, wid = tid >> 5;
    int wm = (wid & 3) * 32, wn = (wid >> 2) * 64;
    int r  = tid >> 1, part = tid & 1;

    uint32_t stRow = (uint32_t)(r * 128);
    uint32_t xld   = (uint32_t)((r & 7) << 4);
    uint32_t xr    = (uint32_t)((lid & 7) << 4);
    uint32_t aSel  = (uint32_t)(((lid >> 4) & 1) << 4);
    uint32_t bSel  = (uint32_t)(((lid >> 3) & 1) << 4);
    uint32_t arb[2], brb[4];
    #pragma unroll
    for (int mt = 0; mt < 2; mt++)
        arb[mt] = (uint32_t)((wm + mt*16 + (lid & 15)) * 128);
    #pragma unroll
    for (int nt = 0; nt < 4; nt++)
        brb[nt] = (uint32_t)((wn + nt*16 + (lid & 7) + (((lid >> 4) & 1) << 3)) * 128);

    // prologue: fill stage 0 with chunk 0
    stage_fill(sb + stRow, aSrc, bSrc, xld, part);

    for (int c = 0; c < 12; c++) {
        CP_WAIT0();          // chunk c landed (issued last iteration / prologue)
        __syncthreads();     // everyone done reading the stage we're about to overwrite
        if (c + 1 < 12) {
            stage_fill(sb + (uint32_t)(((c+1) & 1) * STAGE_BYTES) + stRow,
                       aSrc + (size_t)(c+1)*128, bSrc + (size_t)(c+1)*128, xld, part);
        }
        uint32_t bo = (uint32_t)((c & 1) * STAGE_BYTES);
        #pragma unroll
        for (int kk = 0; kk < 4; kk++) {
            uint32_t cb = (uint32_t)(kk << 5);
            uint32_t ah[2][4];
            #pragma unroll
            for (int mt = 0; mt < 2; mt++)
                LDSM4(ah[mt], sb + bo + arb[mt] + ((cb | aSel) ^ xr));
            #pragma unroll
            for (int nt = 0; nt < 4; nt++) {
                uint32_t bh[4];
                LDSM4(bh, sb + bo + 16384 + brb[nt] + ((cb | bSel) ^ xr));
                #pragma unroll
                for (int n8 = 0; n8 < 2; n8++)
                    #pragma unroll
                    for (int mt = 0; mt < 2; mt++)
                        MMAH(acc[mt][nt*2+n8], ah[mt], bh[n8*2], bh[n8*2+1]);
            }
        }
    }
}

// Stage accumulators into smem as [128][132] f32 (67584 bytes)
static __device__ __forceinline__ void stage_acc(float acc[2][8][4], float* st) {
    int tid = threadIdx.x, lid = tid & 31, wid = tid >> 5;
    int wm = (wid & 3) * 32, wn = (wid >> 2) * 64;
    int qr = lid >> 2, qc = (lid & 3) * 2;
    #pragma unroll
    for (int mt = 0; mt < 2; mt++)
        #pragma unroll
        for (int n8 = 0; n8 < 8; n8++) {
            float* p0 = st + (wm + mt*16 + qr)*132 + wn + n8*8 + qc;
            p0[0] = acc[mt][n8][0];
            p0[1] = acc[mt][n8][1];
            p0[8*132]   = acc[mt][n8][2];
            p0[8*132+1] = acc[mt][n8][3];
        }
}

// ---------------------------------------------------------------------------
// Kernel 4: QKV GEMM
// ---------------------------------------------------------------------------
__global__ void __launch_bounds__(256, 2) qkv_gemm_tc(const float* __restrict__ bias) {
    extern __shared__ char smem[];
    uint32_t sb = smem_u32(smem);
    int tid = threadIdx.x;
    int bn = blockIdx.x * 128, bm = blockIdx.y * 128;
    int r = tid >> 1, part = tid & 1;
    const char* aSrc = (const char*)(g_ah  + (size_t)(bm + r)*C_) + part*64;
    const char* bSrc = (const char*)(g_wih + (size_t)(bn + r)*C_) + part*64;

    float acc[2][8][4] = {};
    mma_mainloop(acc, aSrc, bSrc, sb);
    __syncthreads();
    float* st = (float*)smem;
    stage_acc(acc, st);
    __syncthreads();

    int t = bm >> 11, s = (bm & (SPA-1)) + (tid >> 1);
    int n0 = bn + (tid & 1) * 64;
    int h = n0 / 192, j0 = n0 % 192;
    float* dst = &g_qkv[(((size_t)s*NH + h)*T_ + t)*192 + j0];
    const float* src = st + (tid >> 1)*132 + (tid & 1)*64;
    #pragma unroll
    for (int i = 0; i < 16; i++) {
        float4 v  = *(const float4*)(src + i*4);
        float4 bv = *(const float4*)(bias + n0 + i*4);
        v.x += bv.x; v.y += bv.y; v.z += bv.z; v.w += bv.w;
        *(float4*)(dst + i*4) = v;
    }
}

// ---------------------------------------------------------------------------
// Kernel 5: attention (fp32), writes fp16 output for out GEMM
// ---------------------------------------------------------------------------
__global__ void attn_kernel(const float* __restrict__ qsc, const float* __restrict__ qbi,
                            const float* __restrict__ ksc, const float* __restrict__ kbi,
                            const float* __restrict__ tab) {
    int sh = blockIdx.x;
    int h = sh % NH, s = sh / NH;
    __shared__ float qs[16][65], ks[16][65], vs[16][65], P[16][17];
    int tid = threadIdx.x;
    int row = tid >> 3, part = tid & 7;
    const float* base = g_qkv + (size_t)sh*(T_*192) + row*192 + part*8;

    {
        float v0[8];
        #pragma unroll
        for (int e = 0; e < 8; e++) v0[e] = base[e];
        float sum = 0.f;
        #pragma unroll
        for (int e = 0; e < 8; e++) sum += v0[e];
        sum += __shfl_xor_sync(~0u, sum, 1); sum += __shfl_xor_sync(~0u, sum, 2); sum += __shfl_xor_sync(~0u, sum, 4);
        float mu = sum * (1.f/64.f), var = 0.f;
        #pragma unroll
        for (int e = 0; e < 8; e++) { float d = v0[e]-mu; var += d*d; }
        var += __shfl_xor_sync(~0u, var, 1); var += __shfl_xor_sync(~0u, var, 2); var += __shfl_xor_sync(~0u, var, 4);
        float rr = rsqrtf(var * (1.f/64.f) + 1e-6f);
        #pragma unroll
        for (int e = 0; e < 8; e++) { int j = part*8+e; qs[row][j] = (v0[e]-mu)*rr*qsc[j] + qbi[j]; }
    }
    {
        float v0[8];
        #pragma unroll
        for (int e = 0; e < 8; e++) v0[e] = base[64+e];
        float sum = 0.f;
        #pragma unroll
        for (int e = 0; e < 8; e++) sum += v0[e];
        sum += __shfl_xor_sync(~0u, sum, 1); sum += __shfl_xor_sync(~0u, sum, 2); sum += __shfl_xor_sync(~0u, sum, 4);
        float mu = sum * (1.f/64.f), var = 0.f;
        #pragma unroll
        for (int e = 0; e < 8; e++) { float d = v0[e]-mu; var += d*d; }
        var += __shfl_xor_sync(~0u, var, 1); var += __shfl_xor_sync(~0u, var, 2); var += __shfl_xor_sync(~0u, var, 4);
        float rr = rsqrtf(var * (1.f/64.f) + 1e-6f);
        #pragma unroll
        for (int e = 0; e < 8; e++) { int j = part*8+e; ks[row][j] = (v0[e]-mu)*rr*ksc[j] + kbi[j]; }
    }
    #pragma unroll
    for (int e = 0; e < 8; e++) vs[row][part*8+e] = base[128+e];
    __syncthreads();

    const float inv_log16_x8 = 8.f / logf(16.f);
    for (int e = tid; e < 256; e += 128) {
        int i = e >> 4, j = e & 15;
        float d = 0.f;
        #pragma unroll
        for (int c = 0; c < 64; c++) d += qs[i][c]*ks[j][c];
        int rp = j - i;
        int ret = (rp > 0) ? 16 : 0;
        int n = rp < 0 ? -rp : rp;
        int bkt;
        if (n < 8) bkt = ret + n;
        else {
            int vl = 8 + (int)(logf((float)n * 0.125f) * inv_log16_x8);
            bkt = ret + (vl < 15 ? vl : 15);
        }
        P[i][j] = d * 0.125f + tab[bkt*NH + h];
    }
    __syncthreads();
    if (tid < 16) {
        float m = -1e30f;
        #pragma unroll
        for (int j = 0; j < 16; j++) m = fmaxf(m, P[tid][j]);
        float sum = 0.f;
        #pragma unroll
        for (int j = 0; j < 16; j++) { float e = expf(P[tid][j]-m); P[tid][j] = e; sum += e; }
        float inv = 1.f / sum;
        #pragma unroll
        for (int j = 0; j < 16; j++) P[tid][j] *= inv;
    }
    __syncthreads();

    float o[8] = {0,0,0,0,0,0,0,0};
    #pragma unroll
    for (int t2 = 0; t2 < 16; t2++) {
        float p = P[row][t2];
        #pragma unroll
        for (int e = 0; e < 8; e++) o[e] += p * vs[t2][part*8+e];
    }
    unsigned H[4];
    #pragma unroll
    for (int e = 0; e < 4; e++) {
        __half2 hh = __floats2half2_rn(o[2*e], o[2*e+1]);
        H[e] = *(unsigned*)&hh;
    }
    size_t off = ((size_t)row*SPA + s)*C_ + h*HD + part*8;
    *(uint4*)(g_oh + off) = make_uint4(H[0], H[1], H[2], H[3]);
}

// ---------------------------------------------------------------------------
// Kernel 6: output GEMM + bias + residual
// ---------------------------------------------------------------------------
__global__ void __launch_bounds__(256, 2) out_gemm_tc(const float* __restrict__ x,
                                                      const float* __restrict__ bias,
                                                      float* __restrict__ y) {
    extern __shared__ char smem[];
    uint32_t sb = smem_u32(smem);
    int tid = threadIdx.x;
    int bn = blockIdx.x * 128, bm = blockIdx.y * 128;
    int r = tid >> 1, part = tid & 1;
    const char* aSrc = (const char*)(g_oh  + (size_t)(bm + r)*C_) + part*64;
    const char* bSrc = (const char*)(g_woh + (size_t)(bn + r)*C_) + part*64;

    float acc[2][8][4] = {};
    mma_mainloop(acc, aSrc, bSrc, sb);
    __syncthreads();
    float* st = (float*)smem;
    stage_acc(acc, st);
    __syncthreads();

    int n = bn + (tid >> 1);
    int sh_ = tid & 1;
    int t = bm >> 11, s0 = bm & (SPA-1);
    size_t off = (size_t)t*C_*SPA + (size_t)n*SPA + s0 + sh_*64;
    float bb = bias[n];
    const float* src = st + sh_*64*132 + (n - bn);
    #pragma unroll
    for (int i = 0; i < 64; i += 4) {
        float4 rx = *(const float4*)(x + off + i);
        float4 v = make_float4(src[(i+0)*132], src[(i+1)*132],
                               src[(i+2)*132], src[(i+3)*132]);
        v.x += bb + rx.x; v.y += bb + rx.y; v.z += bb + rx.z; v.w += bb + rx.w;
        *(float4*)(y + off + i) = v;
    }
}

// ---------------------------------------------------------------------------
extern "C" void kernel_launch(void* const* d_in, const int* in_sizes, int n_in,
                              void* d_out, int out_size) {
    const float* x     = (const float*)d_in[0];
    const float* nw    = (const float*)d_in[1];
    const float* w_in  = (const float*)d_in[2];
    const float* b_in  = (const float*)d_in[3];
    const float* qsc   = (const float*)d_in[4];
    const float* qbi   = (const float*)d_in[5];
    const float* ksc   = (const float*)d_in[6];
    const float* kbi   = (const float*)d_in[7];
    const float* tab   = (const float*)d_in[8];
    const float* w_out = (const float*)d_in[9];
    const float* b_out = (const float*)d_in[10];
    float* y = (float*)d_out;

    cudaFuncSetAttribute(qkv_gemm_tc, cudaFuncAttributeMaxDynamicSharedMemorySize, SMEM_GEMM);
    cudaFuncSetAttribute(out_gemm_tc, cudaFuncAttributeMaxDynamicSharedMemorySize, SMEM_GEMM);

    gn_stats_kernel<<<T_*NH, 256>>>(x);
    prep_w_kernel<<<(N1*C_/4 + C_*C_/4)/256, 256>>>(w_in, w_out);
    prep_x_kernel<<<dim3(M_/64, C_/64), 256>>>(x, nw);
    qkv_gemm_tc<<<dim3(N1/128, M_/128), 256, SMEM_GEMM>>>(b_in);
    attn_kernel<<<SPA*NH, 128>>>(qsc, qbi, ksc, kbi, tab);
    out_gemm_tc<<<dim3(C_/128, M_/128), 256, SMEM_GEMM>>>(x, b_out, y);
}